// round 7
// baseline (speedup 1.0000x reference)
#include <cuda_runtime.h>
#include <cstdint>

#define VOCAB 128
#define NTAGS 8
#define EDIM  256
#define HDIM  1024
#define BATCH 1024
#define SEQ   128

// ------------------------- device scratch (static, no allocs) -------------
__device__ float g_Q[VOCAB * HDIM];                       // 512 KB, L2-resident
__device__ int   g_len[BATCH];
__device__ float g_H[(size_t)SEQ * BATCH * HDIM];         // 512 MB: h after step t

// ===========================================================================
// Q[v][h] = sum_e emb[v][e] * W_ih[h][e] + b_ih[h] + b_hh[h]
// ===========================================================================
__global__ void q_kernel(const float* __restrict__ emb,
                         const float* __restrict__ W_ih,
                         const float* __restrict__ b_ih,
                         const float* __restrict__ b_hh) {
    int v = blockIdx.x;
    int warp = threadIdx.x >> 5, lane = threadIdx.x & 31;
    const float* e = emb + v * EDIM;
    for (int h = warp; h < HDIM; h += 8) {
        const float* w = W_ih + h * EDIM;
        float acc = 0.f;
        #pragma unroll
        for (int k = lane; k < EDIM; k += 32) acc += e[k] * w[k];
        #pragma unroll
        for (int o = 16; o > 0; o >>= 1) acc += __shfl_down_sync(0xffffffffu, acc, o);
        if (lane == 0) g_Q[v * HDIM + h] = acc + b_ih[h] + b_hh[h];
    }
}

// ===========================================================================
// seq_lengths + t=0 step (h0 = 0 so pre-activation is just Q[id0])
// ===========================================================================
__global__ void t0_kernel(const int* __restrict__ ids) {
    int b = blockIdx.x, tid = threadIdx.x;
    int m = (ids[b * SEQ + tid] != 0) ? 1 : 0;
    __shared__ int ws[4];
    #pragma unroll
    for (int o = 16; o > 0; o >>= 1) m += __shfl_down_sync(0xffffffffu, m, o);
    if ((tid & 31) == 0) ws[tid >> 5] = m;
    __syncthreads();
    int len = ws[0] + ws[1] + ws[2] + ws[3];
    if (tid == 0) g_len[b] = len;

    int id0 = ids[b * SEQ];
    const float* q = g_Q + (size_t)id0 * HDIM;
    float* hout = g_H + (size_t)b * HDIM;
    for (int h = tid; h < HDIM; h += 128)
        hout[h] = (len > 0) ? tanhf(q[h]) : 0.f;
}

// ===========================================================================
// step_kernel: tf32 m16n8k8, CTA tile 128x64, 512 threads (16 warps).
// CTA-internal split-K: warps 0-7 K[0,512), warps 8-15 K[512,1024).
// KCH=64 per half, 8 chunks, double-buffered smem per half (4 buffers,
// 204 KB total), one barrier per chunk. Partials combined via smem.
// grid = (16, 8) = 128 CTAs.
// ===========================================================================
#define KCH        64
#define NCHK       8                       /* (HDIM/2)/KCH */
#define APITCH     68                      /* 68 ≡ 4 (mod 32): conflict-free */
#define A_FLOATS   (128 * APITCH)          /* 8704 */
#define B_FLOATS   (64  * APITCH)          /* 4352 */
#define BUF_FLOATS (A_FLOATS + B_FLOATS)   /* 13056 floats = 52224 B */
#define CPITCH     36                      /* combine-buffer pitch */
#define STEP_SMEM  (4 * BUF_FLOATS * 4 + 1024)   /* 209920 B */

__device__ __forceinline__ void cp16(float* sp, const float* gp) {
    uint32_t s = (uint32_t)__cvta_generic_to_shared(sp);
    asm volatile("cp.async.cg.shared.global [%0], [%1], 16;\n" :: "r"(s), "l"(gp));
}

__device__ __forceinline__ void mma_tf32(float* d, const uint32_t* a, const uint32_t* b) {
    asm volatile(
        "mma.sync.aligned.m16n8k8.row.col.f32.tf32.tf32.f32 "
        "{%0,%1,%2,%3}, {%4,%5,%6,%7}, {%8,%9}, {%0,%1,%2,%3};\n"
        : "+f"(d[0]), "+f"(d[1]), "+f"(d[2]), "+f"(d[3])
        : "r"(a[0]), "r"(a[1]), "r"(a[2]), "r"(a[3]), "r"(b[0]), "r"(b[1]));
}

extern __shared__ float smem_raw[];

__global__ void __launch_bounds__(512, 1)
step_kernel(const float* __restrict__ W_hh, const int* __restrict__ ids, int t) {
    float* sm = (float*)(((uintptr_t)smem_raw + 1023) & ~(uintptr_t)1023);

    const float* __restrict__ Hprev = g_H + (size_t)(t - 1) * BATCH * HDIM;
    float* __restrict__ Hout        = g_H + (size_t)t       * BATCH * HDIM;

    const int tid  = threadIdx.x;
    const int lane = tid & 31, warp = tid >> 5;
    const int wm = warp & 3, wn = (warp >> 2) & 1, hw = warp >> 3;
    const int g  = lane >> 2, c = lane & 3;
    const int m0 = blockIdx.y * 128;
    const int n0 = blockIdx.x * 64;

    // loader identity (buffer half decoupled from compute role; same split)
    const int lh = tid >> 8, lt = tid & 255;

    float acc[2][4][4] = {};

    // ---- per-chunk stage loader: 12 cp16/thread, one commit group ---------
    #define LOAD(ch)                                                               \
        do {                                                                       \
            float* base = sm + (lh * 2 + ((ch) & 1)) * BUF_FLOATS;                 \
            const int k0_ = lh * 512 + (ch) * KCH;                                 \
            _Pragma("unroll")                                                      \
            for (int i = 0; i < 8; i++) {                                          \
                int j = lt + i * 256;                                              \
                int r = j >> 4, c16 = j & 15;                                      \
                cp16(base + r * APITCH + c16 * 4,                                  \
                     Hprev + (size_t)(m0 + r) * HDIM + k0_ + c16 * 4);             \
            }                                                                      \
            _Pragma("unroll")                                                      \
            for (int i = 0; i < 4; i++) {                                          \
                int j = lt + i * 256;                                              \
                int r = j >> 4, c16 = j & 15;                                      \
                cp16(base + A_FLOATS + r * APITCH + c16 * 4,                       \
                     W_hh + (size_t)(n0 + r) * HDIM + k0_ + c16 * 4);              \
            }                                                                      \
            asm volatile("cp.async.commit_group;\n");                              \
        } while (0)

    #define LDFRAG(da, db, ksv)                                                    \
        do {                                                                       \
            _Pragma("unroll")                                                      \
            for (int mt = 0; mt < 2; mt++) {                                       \
                const float* ap = A + (mt * 16 + g) * APITCH + (ksv) * 8 + c;      \
                da[mt][0] = __float_as_uint(ap[0]);                                \
                da[mt][1] = __float_as_uint(ap[8 * APITCH]);                       \
                da[mt][2] = __float_as_uint(ap[4]);                                \
                da[mt][3] = __float_as_uint(ap[8 * APITCH + 4]);                   \
            }                                                                      \
            _Pragma("unroll")                                                      \
            for (int nt = 0; nt < 4; nt++) {                                       \
                const float* bp = B + (nt * 8 + g) * APITCH + (ksv) * 8 + c;       \
                db[nt][0] = __float_as_uint(bp[0]);                                \
                db[nt][1] = __float_as_uint(bp[4]);                                \
            }                                                                      \
        } while (0)

    LOAD(0);

    for (int ch = 0; ch < NCHK; ch++) {
        asm volatile("cp.async.wait_group 0;\n");
        __syncthreads();
        if (ch + 1 < NCHK) LOAD(ch + 1);

        const float* buf = sm + (hw * 2 + (ch & 1)) * BUF_FLOATS;
        const float* A = buf + (wm * 32) * APITCH;
        const float* B = buf + A_FLOATS + (wn * 32) * APITCH;

        uint32_t af[2][2][4], bf[2][4][2];
        LDFRAG(af[0], bf[0], 0);
        #pragma unroll
        for (int ks = 0; ks < KCH / 8; ks++) {
            const int cur = ks & 1;
            if (ks < KCH / 8 - 1) LDFRAG(af[cur ^ 1], bf[cur ^ 1], ks + 1);
            #pragma unroll
            for (int mt = 0; mt < 2; mt++)
                #pragma unroll
                for (int nt = 0; nt < 4; nt++)
                    mma_tf32(acc[mt][nt], af[cur][mt], bf[cur][nt]);
        }
    }

    // ---- combine split-K halves through smem (reuses buffer 0 region) -----
    // Last chunk (ch=7, odd) read buffers at parity 1; buffer 0 is idle.
    if (warp >= 8) {
        float* cb = sm + ((warp - 8) * 32 + lane) * CPITCH;
        #pragma unroll
        for (int mt = 0; mt < 2; mt++)
            #pragma unroll
            for (int nt = 0; nt < 4; nt++) {
                float4 v = make_float4(acc[mt][nt][0], acc[mt][nt][1],
                                       acc[mt][nt][2], acc[mt][nt][3]);
                *(float4*)(cb + mt * 16 + nt * 4) = v;
            }
    }
    __syncthreads();

    if (warp < 8) {
        const float* cb = sm + (warp * 32 + lane) * CPITCH;
        #pragma unroll
        for (int mt = 0; mt < 2; mt++)
            #pragma unroll
            for (int nt = 0; nt < 4; nt++) {
                float4 v = *(const float4*)(cb + mt * 16 + nt * 4);
                acc[mt][nt][0] += v.x; acc[mt][nt][1] += v.y;
                acc[mt][nt][2] += v.z; acc[mt][nt][3] += v.w;
            }

        // ---- epilogue: + Q gather, tanh, mask (warps 0-7 cover the tile) --
        const int c2 = c * 2;
        #pragma unroll
        for (int mt = 0; mt < 2; mt++) {
            const int rA = m0 + wm * 32 + mt * 16 + g;
            const int rB = rA + 8;
            const int idA = ids[rA * SEQ + t];
            const int idB = ids[rB * SEQ + t];
            const bool mA = t < g_len[rA];
            const bool mB = t < g_len[rB];
            const float* q0 = g_Q + (size_t)idA * HDIM;
            const float* q1 = g_Q + (size_t)idB * HDIM;
            float* o0 = Hout + (size_t)rA * HDIM;
            float* o1 = Hout + (size_t)rB * HDIM;
            const float* p0 = Hprev + (size_t)rA * HDIM;
            const float* p1 = Hprev + (size_t)rB * HDIM;
            #pragma unroll
            for (int nt = 0; nt < 4; nt++) {
                const int n = n0 + wn * 32 + nt * 8 + c2;
                o0[n]     = mA ? tanhf(acc[mt][nt][0] + q0[n])     : p0[n];
                o0[n + 1] = mA ? tanhf(acc[mt][nt][1] + q0[n + 1]) : p0[n + 1];
                o1[n]     = mB ? tanhf(acc[mt][nt][2] + q1[n])     : p1[n];
                o1[n + 1] = mB ? tanhf(acc[mt][nt][3] + q1[n + 1]) : p1[n + 1];
            }
        }
    }
    #undef LOAD
    #undef LDFRAG
}

// ===========================================================================
// y[b][t][tag] = H[t][b][:] . W_out[tag][:] + b_out[tag]
// ===========================================================================
__global__ void y_kernel(const float* __restrict__ W_out,
                         const float* __restrict__ b_out,
                         float* __restrict__ y) {
    __shared__ float sW[NTAGS * HDIM];
    __shared__ float sb[NTAGS];
    for (int i = threadIdx.x; i < NTAGS * HDIM; i += 256) sW[i] = W_out[i];
    if (threadIdx.x < NTAGS) sb[threadIdx.x] = b_out[threadIdx.x];
    __syncthreads();

    const int r = blockIdx.x * 256 + threadIdx.x;   // r = b*SEQ + t
    const int b = r / SEQ, t = r % SEQ;
    const float4* h = (const float4*)(g_H + (size_t)t * BATCH * HDIM + (size_t)b * HDIM);

    float acc[NTAGS];
    #pragma unroll
    for (int tg = 0; tg < NTAGS; tg++) acc[tg] = sb[tg];

    #pragma unroll 4
    for (int k4 = 0; k4 < HDIM / 4; k4++) {
        const float4 hv = h[k4];
        #pragma unroll
        for (int tg = 0; tg < NTAGS; tg++) {
            const float4 wv = ((const float4*)(sW + tg * HDIM))[k4];
            acc[tg] += hv.x * wv.x + hv.y * wv.y + hv.z * wv.z + hv.w * wv.w;
        }
    }
    #pragma unroll
    for (int tg = 0; tg < NTAGS; tg++) y[(size_t)r * NTAGS + tg] = acc[tg];
}

// ===========================================================================
extern "C" void kernel_launch(void* const* d_in, const int* in_sizes, int n_in,
                              void* d_out, int out_size) {
    (void)in_sizes; (void)n_in; (void)out_size;
    const int*   ids   = (const int*)  d_in[0];
    const float* emb   = (const float*)d_in[1];
    const float* W_ih  = (const float*)d_in[2];
    const float* W_hh  = (const float*)d_in[3];
    const float* b_ih  = (const float*)d_in[4];
    const float* b_hh  = (const float*)d_in[5];
    const float* W_out = (const float*)d_in[6];
    const float* b_out = (const float*)d_in[7];
    float* y = (float*)d_out;

    cudaFuncSetAttribute(step_kernel,
                         cudaFuncAttributeMaxDynamicSharedMemorySize, STEP_SMEM);

    q_kernel<<<VOCAB, 256>>>(emb, W_ih, b_ih, b_hh);
    t0_kernel<<<BATCH, 128>>>(ids);
    for (int t = 1; t < SEQ; t++)
        step_kernel<<<dim3(HDIM / 64, BATCH / 128), 512, STEP_SMEM>>>(W_hh, ids, t);
    y_kernel<<<(BATCH * SEQ) / 256, 256>>>(W_out, b_out, y);
}